// round 7
// baseline (speedup 1.0000x reference)
#include <cuda_runtime.h>

// Problem constants
#define IN_SZ   8192
#define OUT_SZ  8192
#define OUT4    (OUT_SZ / 4)            // 2048 float4 columns
// sigmoid(2.0)
#define SIG_TAU 0.8807970779778823f

// Main-kernel tiling — known-good config (R3/R4: ~122.7us main). Loop body unchanged.
#define THREADS          256
#define COLS4_PER_BLOCK  256            // one float4 column per thread
#define GRID_X           (OUT4 / COLS4_PER_BLOCK)   // 8
#define NSLICE           128            // split-K row slices
#define ROWS_PER_SLICE   (IN_SZ / NSLICE)           // 64

// Deterministic split-K scratch (no atomics on data -> bitwise-reproducible spikes). 4 MB.
__device__ float g_partial[NSLICE * OUT_SZ];
// Per-column-group completion counters. atomicInc wraps at NSLICE-1, so each
// counter returns to 0 after every launch -> graph-replay safe.
__device__ unsigned int g_done[GRID_X];

// Single fused kernel:
//   phase 1 (all 8x128 blocks): J_out = SIG_TAU*J + x[i]; split-K partial GEMV
//   phase 2 (last-finishing block per column group): reduce 128 partials in
//            FIXED slice order, LIF update, write u_out and s.
__global__ __launch_bounds__(THREADS, 1)
void ostl_fused_kernel(const float* __restrict__ x,
                       const float* __restrict__ u,
                       const float* __restrict__ J,
                       const float* __restrict__ W,
                       float* __restrict__ Jout,
                       float* __restrict__ out_u,
                       float* __restrict__ out_s)
{
    __shared__ float sx[ROWS_PER_SLICE];
    __shared__ bool  s_last;

    const int c    = blockIdx.x * COLS4_PER_BLOCK + threadIdx.x;  // float4 column
    const int row0 = blockIdx.y * ROWS_PER_SLICE;

    for (int i = threadIdx.x; i < ROWS_PER_SLICE; i += THREADS)
        sx[i] = x[row0 + i];
    __syncthreads();

    const float4* __restrict__ W4 = (const float4*)W;
    const float4* __restrict__ J4 = (const float4*)J;
    float4*       __restrict__ O4 = (float4*)Jout;

    float4 acc = make_float4(0.f, 0.f, 0.f, 0.f);
    int idx = row0 * OUT4 + c;   // max ~16.7M -> fits int

    #pragma unroll 4
    for (int r = 0; r < ROWS_PER_SLICE; ++r, idx += OUT4) {
        const float xi = sx[r];
        const float4 w = W4[idx];
        const float4 j = J4[idx];

        acc.x = fmaf(xi, w.x, acc.x);
        acc.y = fmaf(xi, w.y, acc.y);
        acc.z = fmaf(xi, w.z, acc.z);
        acc.w = fmaf(xi, w.w, acc.w);

        float4 o;
        o.x = fmaf(SIG_TAU, j.x, xi);
        o.y = fmaf(SIG_TAU, j.y, xi);
        o.z = fmaf(SIG_TAU, j.z, xi);
        o.w = fmaf(SIG_TAU, j.w, xi);
        O4[idx] = o;
    }

    // Publish this slice's partial (coalesced float4)
    ((float4*)g_partial)[blockIdx.y * OUT4 + c] = acc;

    // Last-block-done election for this column group
    __threadfence();
    if (threadIdx.x == 0) {
        const unsigned int old = atomicInc(&g_done[blockIdx.x], NSLICE - 1);
        s_last = (old == NSLICE - 1);        // wraps to 0 -> replay-safe
    }
    __syncthreads();
    if (!s_last) return;

    __threadfence();                         // see all other blocks' partials

    // Reduce 128 partials in FIXED slice order -> deterministic despite the
    // nondeterministic election of which block reduces.
    const float4* __restrict__ P4 = (const float4*)g_partial;
    float4 a = make_float4(0.f, 0.f, 0.f, 0.f);
    int pidx = c;
    #pragma unroll 8
    for (int k = 0; k < NSLICE; ++k, pidx += OUT4) {
        const float4 p = P4[pidx];
        a.x += p.x; a.y += p.y; a.z += p.z; a.w += p.w;
    }

    const float4 uu = ((const float4*)u)[c];
    float4 uo, so;
    {
        float un;
        un = fmaf(SIG_TAU, uu.x, a.x); so.x = (un - 1.0f) > 0.f ? 1.f : 0.f; uo.x = un - so.x;
        un = fmaf(SIG_TAU, uu.y, a.y); so.y = (un - 1.0f) > 0.f ? 1.f : 0.f; uo.y = un - so.y;
        un = fmaf(SIG_TAU, uu.z, a.z); so.z = (un - 1.0f) > 0.f ? 1.f : 0.f; uo.z = un - so.z;
        un = fmaf(SIG_TAU, uu.w, a.w); so.w = (un - 1.0f) > 0.f ? 1.f : 0.f; uo.w = un - so.w;
    }
    ((float4*)out_u)[c] = uo;
    ((float4*)out_s)[c] = so;
}

extern "C" void kernel_launch(void* const* d_in, const int* in_sizes, int n_in,
                              void* d_out, int out_size)
{
    const float* x = (const float*)d_in[0];
    const float* u = (const float*)d_in[1];
    const float* J = (const float*)d_in[2];
    const float* W = (const float*)d_in[3];

    float* out   = (float*)d_out;
    float* out_u = out;                                   // [0, 8192)
    float* out_J = out + OUT_SZ;                          // [8192, 8192+64M)
    float* out_s = out + OUT_SZ + (size_t)IN_SZ * OUT_SZ; // last 8192

    dim3 grid(GRID_X, NSLICE);
    ostl_fused_kernel<<<grid, THREADS>>>(x, u, J, W, out_J, out_u, out_s);
}

// round 8
// speedup vs baseline: 1.0628x; 1.0628x over previous
#include <cuda_runtime.h>

// Problem constants
#define IN_SZ   8192
#define OUT_SZ  8192
#define OUT4    (OUT_SZ / 4)            // 2048 float4 columns
// sigmoid(2.0)
#define SIG_TAU 0.8807970779778823f

// Main-kernel tiling: 1024 blocks x 256 threads (proven saturation point),
// reshaped so each block covers 32 float4 columns x 512 rows; the 8 warps
// split the rows (64 rows each -> per-warp access pattern identical to the
// known-good config: 512B contiguous per row, 32KB row stride).
#define THREADS        256
#define WARPS          8
#define SLAB_COLS4     32               // float4 columns per block (one per lane)
#define NSLAB          (OUT4 / SLAB_COLS4)        // 64 column slabs
#define RGROUPS        16               // row groups (split-K depth)
#define ROWS_PER_BLOCK (IN_SZ / RGROUPS)          // 512
#define ROWS_PER_WARP  (ROWS_PER_BLOCK / WARPS)   // 64

// Deterministic split-K scratch: 16 x 2048 float4 = 512 KB (was 4 MB).
__device__ float4 g_partial4[RGROUPS * OUT4];

__global__ __launch_bounds__(THREADS, 1)
void ostl_main_kernel(const float* __restrict__ x,
                      const float* __restrict__ J,
                      const float* __restrict__ W,
                      float* __restrict__ Jout)
{
    __shared__ float  sx[ROWS_PER_BLOCK];              // 2 KB
    __shared__ float4 sacc[WARPS][SLAB_COLS4];         // 4 KB

    const int lane = threadIdx.x & 31;
    const int w    = threadIdx.x >> 5;                 // warp 0..7
    const int c    = blockIdx.x * SLAB_COLS4 + lane;   // float4 column
    const int rg0  = blockIdx.y * ROWS_PER_BLOCK;      // block row base

    for (int i = threadIdx.x; i < ROWS_PER_BLOCK; i += THREADS)
        sx[i] = x[rg0 + i];
    __syncthreads();

    const float4* __restrict__ W4 = (const float4*)W;
    const float4* __restrict__ J4 = (const float4*)J;
    float4*       __restrict__ O4 = (float4*)Jout;

    float4 acc = make_float4(0.f, 0.f, 0.f, 0.f);
    const int rbase = w * ROWS_PER_WARP;               // warp's rows within block
    int idx = (rg0 + rbase) * OUT4 + c;                // max ~16.7M -> fits int

    #pragma unroll 4
    for (int r = 0; r < ROWS_PER_WARP; ++r, idx += OUT4) {
        const float xi = sx[rbase + r];
        const float4 wv = W4[idx];
        const float4 jv = J4[idx];

        acc.x = fmaf(xi, wv.x, acc.x);
        acc.y = fmaf(xi, wv.y, acc.y);
        acc.z = fmaf(xi, wv.z, acc.z);
        acc.w = fmaf(xi, wv.w, acc.w);

        float4 o;
        o.x = fmaf(SIG_TAU, jv.x, xi);
        o.y = fmaf(SIG_TAU, jv.y, xi);
        o.z = fmaf(SIG_TAU, jv.z, xi);
        o.w = fmaf(SIG_TAU, jv.w, xi);
        O4[idx] = o;
    }

    // In-block cross-warp reduction in FIXED warp order -> deterministic.
    sacc[w][lane] = acc;
    __syncthreads();

    if (w == 0) {
        float4 a = sacc[0][lane];
        #pragma unroll
        for (int t = 1; t < WARPS; ++t) {
            const float4 b = sacc[t][lane];
            a.x += b.x; a.y += b.y; a.z += b.z; a.w += b.w;
        }
        // One 512B partial store per block (coalesced)
        g_partial4[blockIdx.y * OUT4 + c] = a;
    }
}

// Epilogue: reduce 16 x 2048 float4 partials (512 KB, mostly L2-warm),
// apply LIF update, emit u_out and s. 64 blocks x 32 threads = 2048 threads,
// one per float4 column; 16 fully-unrolled slice loads (fixed order).
#define EPI_TPB   32
#define EPI_GRID  (OUT4 / EPI_TPB)     // 64 blocks
__global__ __launch_bounds__(EPI_TPB, 1)
void ostl_epilogue_kernel(const float* __restrict__ u,
                          float* __restrict__ out_u,
                          float* __restrict__ out_s)
{
    const int c = blockIdx.x * EPI_TPB + threadIdx.x;   // float4 column

    float4 a = make_float4(0.f, 0.f, 0.f, 0.f);
    #pragma unroll
    for (int k = 0; k < RGROUPS; ++k) {                 // 16 independent loads
        const float4 p = g_partial4[k * OUT4 + c];      // warp reads 512B lines
        a.x += p.x; a.y += p.y; a.z += p.z; a.w += p.w;
    }

    const float4 uu = ((const float4*)u)[c];
    float4 uo, so;
    {
        float un;
        un = fmaf(SIG_TAU, uu.x, a.x); so.x = (un - 1.0f) > 0.f ? 1.f : 0.f; uo.x = un - so.x;
        un = fmaf(SIG_TAU, uu.y, a.y); so.y = (un - 1.0f) > 0.f ? 1.f : 0.f; uo.y = un - so.y;
        un = fmaf(SIG_TAU, uu.z, a.z); so.z = (un - 1.0f) > 0.f ? 1.f : 0.f; uo.z = un - so.z;
        un = fmaf(SIG_TAU, uu.w, a.w); so.w = (un - 1.0f) > 0.f ? 1.f : 0.f; uo.w = un - so.w;
    }
    ((float4*)out_u)[c] = uo;
    ((float4*)out_s)[c] = so;
}

extern "C" void kernel_launch(void* const* d_in, const int* in_sizes, int n_in,
                              void* d_out, int out_size)
{
    const float* x = (const float*)d_in[0];
    const float* u = (const float*)d_in[1];
    const float* J = (const float*)d_in[2];
    const float* W = (const float*)d_in[3];

    float* out   = (float*)d_out;
    float* out_u = out;                                   // [0, 8192)
    float* out_J = out + OUT_SZ;                          // [8192, 8192+64M)
    float* out_s = out + OUT_SZ + (size_t)IN_SZ * OUT_SZ; // last 8192

    dim3 grid(NSLAB, RGROUPS);                            // 64 x 16 = 1024 blocks
    ostl_main_kernel<<<grid, THREADS>>>(x, J, W, out_J);
    ostl_epilogue_kernel<<<EPI_GRID, EPI_TPB>>>(u, out_u, out_s);
}